// round 8
// baseline (speedup 1.0000x reference)
#include <cuda_runtime.h>
#include <math.h>

#define BB 128
#define SS 26
#define AA 5
#define PP 3380   /* 26*26*5 */
#define MM 30
#define TILE 256
#define NT2 7     /* double-tiles per batch: 7 x 512 = 3584 >= 3380 */
#define CWF 16.0f

#define N_PRED 10816000
#define N_TGT  19200
#define N_ANC  10

__device__ unsigned long long g_part[BB * NT2 * MM];
__device__ float  g_confp[BB * NT2];
__device__ double g_bloc[BB];
__device__ double g_bconf[BB];
__device__ int    g_bctr[BB];  // zero at load; reset each run by batch-last block
__device__ int    g_gctr;      // zero at load; reset each run by global-last block

__device__ __forceinline__ float sigf(float x) {
    return 1.0f / (1.0f + __expf(-x));
}
// order-preserving float -> u32 (monotone for all non-NaN floats)
__device__ __forceinline__ unsigned int okey(float f) {
    unsigned int u = __float_as_uint(f);
    return (u & 0x80000000u) ? ~u : (u | 0x80000000u);
}

__global__ __launch_bounds__(TILE) void k_main(
    const float* __restrict__ pred,
    const float* __restrict__ tgt,
    const float* __restrict__ anc,
    float* __restrict__ out)
{
    __shared__ float4 sBox[2 * TILE];      // (x2, y2, x1, y1)
    __shared__ float  sArea[2 * TILE];
    __shared__ float  sTgt[MM * 5];
    __shared__ unsigned long long sMerge[MM];
    __shared__ float  sConf[TILE / 32];

    const int tid  = threadIdx.x;
    const int lane = tid & 31;
    const int warp = tid >> 5;
    const int b    = blockIdx.x / NT2;
    const int dt   = blockIdx.x % NT2;          // double-tile index
    const int pA   = dt * 2 * TILE + tid;       // always < PP (A-tiles full)
    const int pB   = pA + TILE;                 // may exceed PP on last dt
    const int nrecB = min(TILE, PP - (dt * 2 + 1) * TILE);  // 256 or 52
    const float INF = __int_as_float(0x7f800000);

    if (tid < MM * 5) sTgt[tid] = tgt[b * MM * 5 + tid];
    if (tid < MM) sMerge[tid] = 0ull;

    // ---- decode two predictions per thread (batched LDG for MLP) ----
    float pcA = 0.f, pcB = 0.f;
    {
        const float* pvA = pred + ((size_t)b * PP + pA) * 25;
        float a0 = __ldg(pvA + 0), a1 = __ldg(pvA + 1), a2 = __ldg(pvA + 2);
        float a3 = __ldg(pvA + 3), a4 = __ldg(pvA + 4);
        float b0 = 0.f, b1 = 0.f, b2 = 0.f, b3 = 0.f, b4 = 0.f;
        const bool hasB = tid < nrecB;
        if (hasB) {
            const float* pvB = pred + ((size_t)b * PP + pB) * 25;
            b0 = __ldg(pvB + 0); b1 = __ldg(pvB + 1); b2 = __ldg(pvB + 2);
            b3 = __ldg(pvB + 3); b4 = __ldg(pvB + 4);
        }
        {
            int a = pA % AA, rem = pA / AA;
            float bw = __expf(0.5f * sigf(a2)) * __ldg(&anc[2 * a])     * CWF;
            float bh = __expf(0.5f * sigf(a3)) * __ldg(&anc[2 * a + 1]) * CWF;
            float bx = (sigf(a0) + (float)(rem % SS)) * CWF;
            float by = (sigf(a1) + (float)(rem / SS)) * CWF;
            float hw = 0.5f * bw, hh = 0.5f * bh;
            sBox[tid]  = make_float4(bx + hw, by + hh, bx - hw, by - hh);
            sArea[tid] = bw * bh;
            pcA = sigf(a4);
        }
        if (hasB) {
            int a = pB % AA, rem = pB / AA;
            float bw = __expf(0.5f * sigf(b2)) * __ldg(&anc[2 * a])     * CWF;
            float bh = __expf(0.5f * sigf(b3)) * __ldg(&anc[2 * a + 1]) * CWF;
            float bx = (sigf(b0) + (float)(rem % SS)) * CWF;
            float by = (sigf(b1) + (float)(rem / SS)) * CWF;
            float hw = 0.5f * bw, hh = 0.5f * bh;
            sBox[TILE + tid]  = make_float4(bx + hw, by + hh, bx - hw, by - hh);
            sArea[TILE + tid] = bw * bh;
            pcB = sigf(b4);
        }
    }
    __syncthreads();

    // ---- GT box per lane (lane = annotation m) ----
    float gx1, gx2, gy1, gy2, s;
    {
        bool v = false;
        float x1 = 0.f, y1 = 0.f, w = 0.f, h = 0.f;
        if (lane < MM) {
            x1 = sTgt[lane * 5 + 0]; y1 = sTgt[lane * 5 + 1];
            w  = sTgt[lane * 5 + 2]; h  = sTgt[lane * 5 + 3];
            v  = (sTgt[lane * 5 + 4] == 1.0f);
        }
        float gxc = x1 + 0.5f * w;
        float gyc = y1 + 0.5f * h;
        float gw  = w - x1;      // faithful to source
        float gh  = h * y1;      // faithful to source
        gx1 = gxc - 0.5f * gw; gx2 = gxc + 0.5f * gw;
        gy1 = gyc - 0.5f * gh; gy2 = gyc + 0.5f * gh;
        s = gw * gh + 1e-9f;
        if (!v) { gx1 = INF; gx2 = -INF; gy1 = INF; gy2 = -INF; s = 1e-9f; }
    }

    // ---- IoU sweeps over both sub-tiles; lane = m, warp covers 32 preds ----
    // Within a lane, IEEE '>' keeps first index on ties (argmax parity);
    // -0.0 canonicalized once at key-pack time for cross-warp merge.
    float best = -INF;
    int   bestp = 0;
    unsigned maskA = 0, maskB = 0;
    const int baseA = warp * 32;
    const int pwA = dt * 2 * TILE + baseA;

    #pragma unroll
    for (int j = 0; j < 32; ++j) {
        float4 bx = sBox[baseA + j];      // broadcast LDS.128
        float  ap = sArea[baseA + j];     // broadcast LDS.32
        float dx = fmaxf(fminf(gx2, bx.x) - fmaxf(gx1, bx.z), 0.f);
        float dy = fmaxf(fminf(gy2, bx.y) - fmaxf(gy1, bx.w), 0.f);
        float inter = dx * dy;
        float iou = __fdividef(inter, (s + ap) - inter);
        if (iou > 0.6f) maskA |= (1u << j);
        if (iou > best) { best = iou; bestp = pwA + j; }
    }
    {
        int jcnt = nrecB - baseA;
        if (jcnt > 32) jcnt = 32;
        if (jcnt == 32) {
            #pragma unroll
            for (int j = 0; j < 32; ++j) {
                float4 bx = sBox[TILE + baseA + j];
                float  ap = sArea[TILE + baseA + j];
                float dx = fmaxf(fminf(gx2, bx.x) - fmaxf(gx1, bx.z), 0.f);
                float dy = fmaxf(fminf(gy2, bx.y) - fmaxf(gy1, bx.w), 0.f);
                float inter = dx * dy;
                float iou = __fdividef(inter, (s + ap) - inter);
                if (iou > 0.6f) maskB |= (1u << j);
                if (iou > best) { best = iou; bestp = pwA + TILE + j; }
            }
        } else {
            for (int j = 0; j < jcnt; ++j) {
                float4 bx = sBox[TILE + baseA + j];
                float  ap = sArea[TILE + baseA + j];
                float dx = fmaxf(fminf(gx2, bx.x) - fmaxf(gx1, bx.z), 0.f);
                float dy = fmaxf(fminf(gy2, bx.y) - fmaxf(gy1, bx.w), 0.f);
                float inter = dx * dy;
                float iou = __fdividef(inter, (s + ap) - inter);
                if (iou > 0.6f) maskB |= (1u << j);
                if (iou > best) { best = iou; bestp = pwA + TILE + j; }
            }
        }
    }
    unsigned objA = __reduce_or_sync(0xFFFFFFFFu, maskA);
    unsigned objB = __reduce_or_sync(0xFFFFFFFFu, maskB);
    bool objMyA = (objA >> lane) & 1u;
    bool objMyB = (objB >> lane) & 1u;

    if (lane < MM) {
        if (__float_as_uint(best) == 0x80000000u) best = 0.0f;  // -0 -> +0
        unsigned long long pk =
            ((unsigned long long)okey(best) << 32) | (unsigned int)(~bestp);
        atomicMax(&sMerge[lane], pk);
    }

    // ---- conf partial (terms recomputed from stashed pc; fixed order) ----
    float acc = objMyA ? (pcA - 1.f) * (pcA - 1.f) : 0.5f * pcA * pcA;
    if (tid < nrecB)
        acc += objMyB ? (pcB - 1.f) * (pcB - 1.f) : 0.5f * pcB * pcB;
    #pragma unroll
    for (int o = 16; o; o >>= 1) acc += __shfl_down_sync(0xFFFFFFFFu, acc, o);
    if (lane == 0) sConf[warp] = acc;
    __syncthreads();

    // ---- warp 0 publishes, then maybe runs the per-batch tail ----
    if (warp != 0) return;

    if (lane < MM) g_part[(size_t)blockIdx.x * MM + lane] = sMerge[lane];
    {
        float v = (lane < TILE / 32) ? sConf[lane] : 0.f;
        #pragma unroll
        for (int o = 4; o; o >>= 1) v += __shfl_down_sync(0xFFFFFFFFu, v, o);
        if (lane == 0) g_confp[blockIdx.x] = v;
    }
    __threadfence();
    __syncwarp();
    int cnt = 0;
    if (lane == 0) cnt = atomicAdd(&g_bctr[b], 1);
    cnt = __shfl_sync(0xFFFFFFFFu, cnt, 0);
    if (cnt != NT2 - 1) return;

    // ===== per-batch post (last-arriving block of batch b) =====
    unsigned long long bk = 0ull;
    float x1 = 0.f, y1 = 0.f, w = 0.f, h = 0.f;
    bool valid = false;
    if (lane < MM) {
        x1 = sTgt[lane * 5 + 0]; y1 = sTgt[lane * 5 + 1];
        w  = sTgt[lane * 5 + 2]; h  = sTgt[lane * 5 + 3];
        valid = (sTgt[lane * 5 + 4] == 1.0f);
        #pragma unroll
        for (int k = 0; k < NT2; ++k) {
            unsigned long long v = __ldcg(&g_part[((size_t)b * NT2 + k) * MM + lane]);
            if (v > bk) bk = v;
        }
    }
    int p = valid ? (int)(~(unsigned int)bk) : (0x10000 + lane);

    // scatter .set semantics: same flat index -> highest m (last write) wins
    unsigned grp = __match_any_sync(0xFFFFFFFFu, p);
    bool writer = valid && (lane == 31 - __clz(grp));

    float term = 0.f;
    if (writer) {
        int ra = p % AA, rw = (p / AA) % SS, rh = p / (AA * SS);
        float gxc = x1 + 0.5f * w;
        float gyc = y1 + 0.5f * h;
        float vx = (gxc - (float)rw * CWF) / CWF;
        float vy = (gyc - (float)rh * CWF) / CWF;
        float vw_ = logf((w / CWF) / __ldg(&anc[2 * ra]));
        float vh_ = logf((h / CWF) / __ldg(&anc[2 * ra + 1]));
        const float* pv = pred + ((size_t)b * PP + p) * 25;
        float p0 = 1.f   / (1.f + expf(-pv[0]));
        float p1 = 1.f   / (1.f + expf(-pv[1]));
        float p2 = 0.5f  / (1.f + expf(-pv[2]));
        float p3 = 0.5f  / (1.f + expf(-pv[3]));
        float d0 = p0 - vx, d1 = p1 - vy, d2 = p2 - vw_, d3 = p3 - vh_;
        term = d0 * d0 + d1 * d1 + d2 * d2 + d3 * d3;
    }
    float cpart = (lane < NT2) ? __ldcg(&g_confp[b * NT2 + lane]) : 0.f;
    #pragma unroll
    for (int o = 16; o; o >>= 1) {
        term  += __shfl_down_sync(0xFFFFFFFFu, term,  o);
        cpart += __shfl_down_sync(0xFFFFFFFFu, cpart, o);
    }

    int done = 0;
    if (lane == 0) {
        g_bctr[b] = 0;                 // reset for next launch
        g_bloc[b]  = (double)term;
        g_bconf[b] = (double)cpart;
        __threadfence();
        done = atomicAdd(&g_gctr, 1);
    }
    done = __shfl_sync(0xFFFFFFFFu, done, 0);
    if (done != BB - 1) return;

    // ===== global finalize (deterministic fixed-order reduce) =====
    double l = 0.0, c = 0.0;
    for (int i = lane; i < BB; i += 32) {
        l += __ldcg(&g_bloc[i]);
        c += __ldcg(&g_bconf[i]);
    }
    #pragma unroll
    for (int o = 16; o; o >>= 1) {
        l += __shfl_down_sync(0xFFFFFFFFu, l, o);
        c += __shfl_down_sync(0xFFFFFFFFu, c, o);
    }
    if (lane == 0) {
        double loc  = 5.0 * l / (double)BB;
        double conf = c / (double)BB;
        out[0] = (float)(loc + conf);
        out[1] = (float)loc;
        out[2] = (float)conf;
        g_gctr = 0;                    // reset for next launch
    }
}

extern "C" void kernel_launch(void* const* d_in, const int* in_sizes, int n_in,
                              void* d_out, int out_size)
{
    const float* pred = 0;
    const float* tgt  = 0;
    const float* anc  = 0;
    for (int i = 0; i < n_in; ++i) {
        if (in_sizes[i] == N_PRED)      pred = (const float*)d_in[i];
        else if (in_sizes[i] == N_TGT)  tgt  = (const float*)d_in[i];
        else if (in_sizes[i] == N_ANC)  anc  = (const float*)d_in[i];
    }
    float* out = (float*)d_out;

    k_main<<<BB * NT2, TILE>>>(pred, tgt, anc, out);
}